// round 10
// baseline (speedup 1.0000x reference)
#include <cuda_runtime.h>
#include <cuda_bf16.h>
#include <cstdint>

// ---------------------------------------------------------------------------
// BipartiteGATConv — round 10: GEMMs on warp-level mma.sync (bf16 hi/lo split,
// fp32 accumulate). tcgen05 is unreachable (harness builds compute_103, not
// compute_103a). CSR/aggr/stream-fork launcher identical to round 8 (verified).
//   D = (Ahi+Alo)@(Bhi+Blo)^T ~= Ahi@Bhi + Ahi@Blo + Alo@Bhi
// ---------------------------------------------------------------------------

#define MAX_N   50000
#define MAX_E   800000
#define FDIM    128
#define HEADS   4
#define SCAN_TILE 1024
#define MAX_SB  ((MAX_N + SCAN_TILE - 1) / SCAN_TILE)

__device__ __align__(16) float g_feat[MAX_N * FDIM];
__device__ __align__(16) float g_asrc[MAX_N * HEADS];
__device__ __align__(16) float g_adst[MAX_N * HEADS];
__device__ __align__(16) float g_fold_v[FDIM * HEADS];
__device__ __align__(16) int   g_deg[MAX_N];
__device__ int   g_row[MAX_N + 1];
__device__ int   g_cursor[MAX_N];
__device__ int   g_bsum[MAX_SB];
__device__ int   g_boff[MAX_SB];
__device__ int   g_csr_s[MAX_E];

__device__ __forceinline__ float leaky02(float z) {
    return z > 0.f ? z : 0.2f * z;
}

#define MMA_BF16(c, a, b) \
    asm volatile("mma.sync.aligned.m16n8k16.row.col.f32.bf16.bf16.f32 " \
        "{%0,%1,%2,%3},{%4,%5,%6,%7},{%8,%9},{%0,%1,%2,%3};" \
        : "+f"((c)[0]), "+f"((c)[1]), "+f"((c)[2]), "+f"((c)[3]) \
        : "r"((a)[0]), "r"((a)[1]), "r"((a)[2]), "r"((a)[3]), \
          "r"((b)[0]), "r"((b)[1]))

// ---------------- fold
__global__ void fold_kernel(const float* __restrict__ W_dst,
                            const float* __restrict__ att_dst) {
    int k = threadIdx.x;
    #pragma unroll
    for (int h = 0; h < HEADS; h++) {
        float s = 0.f;
        #pragma unroll 8
        for (int d = 0; d < 32; d++)
            s += W_dst[k * FDIM + h * 32 + d] * att_dst[h * 32 + d];
        g_fold_v[k * HEADS + h] = s;
    }
}

// ---------------- CSR build (unchanged, verified) ----------------
__global__ void zero_deg_kernel(int n) {
    int i = blockIdx.x * blockDim.x + threadIdx.x;
    if (i < n) g_deg[i] = 0;
}

__global__ void hist_kernel(const int* __restrict__ ed, int E) {
    int e = blockIdx.x * blockDim.x + threadIdx.x;
    if (e < E) atomicAdd(&g_deg[ed[e]], 1);
}

__global__ __launch_bounds__(256)
void scan_local_kernel(int n) {
    __shared__ int warp_tot[8];
    int t = threadIdx.x;
    int lane = t & 31, w = t >> 5;
    int base = blockIdx.x * SCAN_TILE + t * 4;

    int4 v = make_int4(0, 0, 0, 0);
    if (base + 3 < n) {
        v = *(const int4*)(g_deg + base);
    } else if (base < n) {
        v.x = g_deg[base];
        if (base + 1 < n) v.y = g_deg[base + 1];
        if (base + 2 < n) v.z = g_deg[base + 2];
    }
    int tot = v.x + v.y + v.z + v.w;

    int inc = tot;
    #pragma unroll
    for (int off = 1; off < 32; off <<= 1) {
        int x = __shfl_up_sync(0xffffffffu, inc, off);
        if (lane >= off) inc += x;
    }
    if (lane == 31) warp_tot[w] = inc;
    __syncthreads();
    if (t < 8) {
        int x = warp_tot[t];
        #pragma unroll
        for (int off = 1; off < 8; off <<= 1) {
            int y = __shfl_up_sync(0xffu, x, off);
            if (t >= off) x += y;
        }
        warp_tot[t] = x;
    }
    __syncthreads();

    int excl = (w > 0 ? warp_tot[w - 1] : 0) + (inc - tot);
    if (base < n) {
        g_row[base] = excl;
        if (base + 1 < n) g_row[base + 1] = excl + v.x;
        if (base + 2 < n) g_row[base + 2] = excl + v.x + v.y;
        if (base + 3 < n) g_row[base + 3] = excl + v.x + v.y + v.z;
    }
    if (t == 0) g_bsum[blockIdx.x] = warp_tot[7];
}

__global__ __launch_bounds__(256)
void scan_bsum_kernel(int nb, int n) {
    __shared__ int s[256];
    int t = threadIdx.x;
    s[t] = (t < nb) ? g_bsum[t] : 0;
    __syncthreads();
    #pragma unroll
    for (int off = 1; off < 256; off <<= 1) {
        int v = (t >= off) ? s[t - off] : 0;
        __syncthreads();
        s[t] += v;
        __syncthreads();
    }
    if (t < nb) g_boff[t] = (t > 0) ? s[t - 1] : 0;
    if (t == 0) g_row[n] = s[255];
}

__global__ __launch_bounds__(256)
void scan_apply_kernel(int n) {
    int t = threadIdx.x;
    int base = blockIdx.x * SCAN_TILE + t * 4;
    int off = g_boff[blockIdx.x];
    #pragma unroll
    for (int j = 0; j < 4; j++) {
        int i = base + j;
        if (i < n) {
            int r = g_row[i] + off;
            g_row[i] = r;
            g_cursor[i] = r;
        }
    }
}

__global__ void scatter_kernel(const int* __restrict__ es,
                               const int* __restrict__ ed, int E) {
    int e = blockIdx.x * blockDim.x + threadIdx.x;
    if (e >= E) return;
    int pos = atomicAdd(&g_cursor[ed[e]], 1);
    g_csr_s[pos] = es[e];
}

// ---------------- aggregate (unchanged, verified)
__global__ __launch_bounds__(256)
void aggr_kernel(float* __restrict__ out, int n_dst) {
    int d = (blockIdx.x * blockDim.x + threadIdx.x) >> 5;
    int lane = threadIdx.x & 31;
    if (d >= n_dst) return;
    int h = lane >> 3;

    int i   = g_row[d];
    int end = g_row[d + 1];
    float adv = g_adst[d * HEADS + h];

    float4 acc = make_float4(0.f, 0.f, 0.f, 0.f);
    float wsum = 0.f;
    const float4* feat4 = (const float4*)g_feat;

    int   s_cur = (i < end) ? g_csr_s[i] : 0;
    float a_cur = (i < end) ? g_asrc[s_cur * HEADS + h] : 0.f;
    for (; i < end; ) {
        int inext = i + 1;
        int   s_nxt = 0;
        float a_nxt = 0.f;
        if (inext < end) {
            s_nxt = g_csr_s[inext];
            a_nxt = g_asrc[s_nxt * HEADS + h];
        }
        float w = __expf(leaky02(a_cur + adv));
        float4 f = feat4[s_cur * 32 + lane];
        acc.x += w * f.x; acc.y += w * f.y;
        acc.z += w * f.z; acc.w += w * f.w;
        wsum += w;
        s_cur = s_nxt; a_cur = a_nxt;
        i = inext;
    }

    float rs = 1.f / (wsum + 1e-16f);
    float4* out4 = (float4*)out;
    float4 o = out4[d * 32 + lane];
    o.x += acc.x * rs; o.y += acc.y * rs;
    o.z += acc.z * rs; o.w += acc.w * rs;
    out4[d * 32 + lane] = o;
}

// ================== mma.sync GEMM: C[128x128 tile] = A @ W ==================
// A tile [m][k] bf16 hi/lo; B tile [n][k] bf16 hi/lo (W transposed on load).
// 8 warps: warp_m = wid&1 (64 rows), warp_n = wid>>1 (32 cols = one head).
// MODE 0: C=feat, alpha_src from C frags.  MODE 1: C=out+bias, alpha_dst from A.
#define KS 136   // padded row stride in bf16 (conflict-free frag loads)
#define TILE_BF16 (128 * KS)
#define SM_GEMM_BYTES (4 * TILE_BF16 * 2 + 640 * 4)

template <int MODE>
__global__ __launch_bounds__(256, 1)
void gemm_mma_kernel(const float* __restrict__ A,
                     const float* __restrict__ W,     // [K=128, N=128]
                     const float* __restrict__ aux,   // att_src (M0) / bias (M1)
                     float* __restrict__ C,
                     float* __restrict__ alpha_out,
                     int nrows) {
    extern __shared__ char smem[];
    __nv_bfloat16* Ah = (__nv_bfloat16*)smem;
    __nv_bfloat16* Al = Ah + TILE_BF16;
    __nv_bfloat16* Bh = Al + TILE_BF16;
    __nv_bfloat16* Bl = Bh + TILE_BF16;
    float* xtra = (float*)(Bl + TILE_BF16);   // [0:128) att/bias, [128:640) fold

    int tid = threadIdx.x;
    int wid = tid >> 5, lane = tid & 31;
    int m0 = blockIdx.x * 128;

    if (tid < FDIM) xtra[tid] = aux[tid];
    if (MODE == 1) {
        for (int i = tid; i < FDIM * HEADS; i += 256) xtra[128 + i] = g_fold_v[i];
    }

    // A: split fp32 -> bf16 hi/lo, [m][k]
    for (int idx = tid; idx < 128 * 128; idx += 256) {
        int row = idx >> 7, col = idx & 127;
        int grow = m0 + row;
        float v = (grow < nrows) ? A[(size_t)grow * FDIM + col] : 0.f;
        __nv_bfloat16 hi = __float2bfloat16(v);
        __nv_bfloat16 lo = __float2bfloat16(v - __bfloat162float(hi));
        Ah[row * KS + col] = hi;
        Al[row * KS + col] = lo;
    }
    // B: [n][k] = W[k][n] transposed (gmem read coalesced over n)
    for (int idx = tid; idx < 128 * 128; idx += 256) {
        int k = idx >> 7, n = idx & 127;
        float v = W[(size_t)k * FDIM + n];
        __nv_bfloat16 hi = __float2bfloat16(v);
        __nv_bfloat16 lo = __float2bfloat16(v - __bfloat162float(hi));
        Bh[n * KS + k] = hi;
        Bl[n * KS + k] = lo;
    }
    __syncthreads();

    int wm = wid & 1, wn = wid >> 1;
    int g = lane >> 2, q = lane & 3;

    float c[4][4][4];
    #pragma unroll
    for (int mf = 0; mf < 4; mf++)
        #pragma unroll
        for (int nf = 0; nf < 4; nf++)
            #pragma unroll
            for (int r = 0; r < 4; r++) c[mf][nf][r] = 0.f;

    #pragma unroll
    for (int kb = 0; kb < 128; kb += 16) {
        uint32_t ah[4][4], al[4][4], bh[4][2], bl[4][2];
        #pragma unroll
        for (int mf = 0; mf < 4; mf++) {
            int r = wm * 64 + mf * 16 + g;
            const __nv_bfloat16* ph = Ah + r * KS + kb + q * 2;
            const __nv_bfloat16* pl = Al + r * KS + kb + q * 2;
            ah[mf][0] = *(const uint32_t*)ph;
            ah[mf][1] = *(const uint32_t*)(ph + 8 * KS);
            ah[mf][2] = *(const uint32_t*)(ph + 8);
            ah[mf][3] = *(const uint32_t*)(ph + 8 * KS + 8);
            al[mf][0] = *(const uint32_t*)pl;
            al[mf][1] = *(const uint32_t*)(pl + 8 * KS);
            al[mf][2] = *(const uint32_t*)(pl + 8);
            al[mf][3] = *(const uint32_t*)(pl + 8 * KS + 8);
        }
        #pragma unroll
        for (int nf = 0; nf < 4; nf++) {
            int n = wn * 32 + nf * 8 + g;
            const __nv_bfloat16* ph = Bh + n * KS + kb + q * 2;
            const __nv_bfloat16* pl = Bl + n * KS + kb + q * 2;
            bh[nf][0] = *(const uint32_t*)ph;
            bh[nf][1] = *(const uint32_t*)(ph + 8);
            bl[nf][0] = *(const uint32_t*)pl;
            bl[nf][1] = *(const uint32_t*)(pl + 8);
        }
        #pragma unroll
        for (int mf = 0; mf < 4; mf++)
            #pragma unroll
            for (int nf = 0; nf < 4; nf++) {
                MMA_BF16(c[mf][nf], ah[mf], bh[nf]);
                MMA_BF16(c[mf][nf], ah[mf], bl[nf]);
                MMA_BF16(c[mf][nf], al[mf], bh[nf]);
            }
    }

    // epilogue: store C (+bias for MODE 1)
    #pragma unroll
    for (int mf = 0; mf < 4; mf++) {
        int row0 = m0 + wm * 64 + mf * 16 + g;
        #pragma unroll
        for (int nf = 0; nf < 4; nf++) {
            int col = wn * 32 + nf * 8 + q * 2;
            float v0 = c[mf][nf][0], v1 = c[mf][nf][1];
            float v2 = c[mf][nf][2], v3 = c[mf][nf][3];
            if (MODE == 1) {
                v0 += xtra[col]; v1 += xtra[col + 1];
                v2 += xtra[col]; v3 += xtra[col + 1];
            }
            if (row0 < nrows)
                *(float2*)(C + (size_t)row0 * FDIM + col) = make_float2(v0, v1);
            if (row0 + 8 < nrows)
                *(float2*)(C + (size_t)(row0 + 8) * FDIM + col) = make_float2(v2, v3);
        }
    }

    if (MODE == 0) {
        // alpha_src: head = wn; reduce over warp's 32 cols
        int h = wn;
        #pragma unroll
        for (int mf = 0; mf < 4; mf++) {
            float p0 = 0.f, p1 = 0.f;
            #pragma unroll
            for (int nf = 0; nf < 4; nf++) {
                int col = wn * 32 + nf * 8 + q * 2;
                p0 += c[mf][nf][0] * xtra[col] + c[mf][nf][1] * xtra[col + 1];
                p1 += c[mf][nf][2] * xtra[col] + c[mf][nf][3] * xtra[col + 1];
            }
            p0 += __shfl_xor_sync(0xffffffffu, p0, 1);
            p0 += __shfl_xor_sync(0xffffffffu, p0, 2);
            p1 += __shfl_xor_sync(0xffffffffu, p1, 1);
            p1 += __shfl_xor_sync(0xffffffffu, p1, 2);
            if (q == 0) {
                int row0 = m0 + wm * 64 + mf * 16 + g;
                if (row0 < nrows)     alpha_out[row0 * HEADS + h] = p0;
                if (row0 + 8 < nrows) alpha_out[(row0 + 8) * HEADS + h] = p1;
            }
        }
    } else {
        // alpha_dst = x @ fold_v, x recovered from hi+lo SMEM
        if (tid < 128) {
            int row = tid;
            int grow = m0 + row;
            if (grow < nrows) {
                float a0 = 0.f, a1 = 0.f, a2 = 0.f, a3 = 0.f;
                for (int k = 0; k < 128; k++) {
                    float x = __bfloat162float(Ah[row * KS + k])
                            + __bfloat162float(Al[row * KS + k]);
                    a0 += x * xtra[128 + k * 4 + 0];
                    a1 += x * xtra[128 + k * 4 + 1];
                    a2 += x * xtra[128 + k * 4 + 2];
                    a3 += x * xtra[128 + k * 4 + 3];
                }
                ((float4*)alpha_out)[grow] = make_float4(a0, a1, a2, a3);
            }
        }
    }
}

// ---------------------------------------------------------------------------
extern "C" void kernel_launch(void* const* d_in, const int* in_sizes, int n_in,
                              void* d_out, int out_size) {
    const float* x_src    = (const float*)d_in[0];
    const float* x_dst    = (const float*)d_in[1];
    const int*   edge_src = (const int*)d_in[2];
    const int*   edge_dst = (const int*)d_in[3];
    int off = (n_in >= 11) ? 5 : 4;
    const float* W_src   = (const float*)d_in[off + 0];
    const float* W_dst   = (const float*)d_in[off + 1];
    const float* att_src = (const float*)d_in[off + 2];
    const float* att_dst = (const float*)d_in[off + 3];
    const float* W_self  = (const float*)d_in[off + 4];
    const float* b_self  = (const float*)d_in[off + 5];
    float* out = (float*)d_out;

    int n_src = in_sizes[0] / FDIM;
    int n_dst = in_sizes[1] / FDIM;
    int E     = in_sizes[2];

    static float* p_feat = nullptr;
    static float* p_asrc = nullptr;
    static float* p_adst = nullptr;
    static cudaStream_t s1 = nullptr, s2 = nullptr;
    static cudaEvent_t ev_fork = nullptr, ev_g1 = nullptr, ev_csr = nullptr;
    if (!p_feat) {
        cudaGetSymbolAddress((void**)&p_feat, g_feat);
        cudaGetSymbolAddress((void**)&p_asrc, g_asrc);
        cudaGetSymbolAddress((void**)&p_adst, g_adst);
        cudaStreamCreateWithFlags(&s1, cudaStreamNonBlocking);
        cudaStreamCreateWithFlags(&s2, cudaStreamNonBlocking);
        cudaEventCreateWithFlags(&ev_fork, cudaEventDisableTiming);
        cudaEventCreateWithFlags(&ev_g1,   cudaEventDisableTiming);
        cudaEventCreateWithFlags(&ev_csr,  cudaEventDisableTiming);
        cudaFuncSetAttribute(gemm_mma_kernel<0>,
            cudaFuncAttributeMaxDynamicSharedMemorySize, SM_GEMM_BYTES);
        cudaFuncSetAttribute(gemm_mma_kernel<1>,
            cudaFuncAttributeMaxDynamicSharedMemorySize, SM_GEMM_BYTES);
    }

    int nb = (n_dst + SCAN_TILE - 1) / SCAN_TILE;

    // main: fold (needed by gemm<1>)
    fold_kernel<<<1, 128>>>(W_dst, att_dst);

    cudaEventRecord(ev_fork, 0);
    cudaStreamWaitEvent(s1, ev_fork, 0);
    cudaStreamWaitEvent(s2, ev_fork, 0);

    // s2: CSR build
    zero_deg_kernel<<<(n_dst + 255) / 256, 256, 0, s2>>>(n_dst);
    hist_kernel<<<(E + 255) / 256, 256, 0, s2>>>(edge_dst, E);
    scan_local_kernel<<<nb, 256, 0, s2>>>(n_dst);
    scan_bsum_kernel<<<1, 256, 0, s2>>>(nb, n_dst);
    scan_apply_kernel<<<nb, 256, 0, s2>>>(n_dst);
    scatter_kernel<<<(E + 255) / 256, 256, 0, s2>>>(edge_src, edge_dst, E);
    cudaEventRecord(ev_csr, s2);

    // s1: dst GEMM (out self-term + alpha_dst)
    gemm_mma_kernel<1><<<(n_dst + 127) / 128, 256, SM_GEMM_BYTES, s1>>>(
        x_dst, W_self, b_self, out, p_adst, n_dst);
    cudaEventRecord(ev_g1, s1);

    // main: src GEMM (feat + alpha_src)
    gemm_mma_kernel<0><<<(n_src + 127) / 128, 256, SM_GEMM_BYTES>>>(
        x_src, W_src, att_src, p_feat, p_asrc, n_src);

    // join
    cudaStreamWaitEvent(0, ev_g1, 0);
    cudaStreamWaitEvent(0, ev_csr, 0);
    long long total_threads = (long long)n_dst * 32;
    int blocks = (int)((total_threads + 255) / 256);
    aggr_kernel<<<blocks, 256>>>(out, n_dst);
}

// round 11
// speedup vs baseline: 1.0605x; 1.0605x over previous
#include <cuda_runtime.h>
#include <cuda_bf16.h>
#include <cstdint>

// ---------------------------------------------------------------------------
// BipartiteGATConv — round 11: round-10 HMMA GEMM (verified numerics) with
// proper fragment feeding: ldmatrix x4 / x4.trans + vectorized staging.
//   D = (Ahi+Alo)@(Bhi+Blo)^T ~= Ahi@Bhi + Ahi@Blo + Alo@Bhi
// CSR/aggr/stream-fork launcher identical to round 8 (verified).
// ---------------------------------------------------------------------------

#define MAX_N   50000
#define MAX_E   800000
#define FDIM    128
#define HEADS   4
#define SCAN_TILE 1024
#define MAX_SB  ((MAX_N + SCAN_TILE - 1) / SCAN_TILE)

__device__ __align__(16) float g_feat[MAX_N * FDIM];
__device__ __align__(16) float g_asrc[MAX_N * HEADS];
__device__ __align__(16) float g_adst[MAX_N * HEADS];
__device__ __align__(16) float g_fold_v[FDIM * HEADS];
__device__ __align__(16) int   g_deg[MAX_N];
__device__ int   g_row[MAX_N + 1];
__device__ int   g_cursor[MAX_N];
__device__ int   g_bsum[MAX_SB];
__device__ int   g_boff[MAX_SB];
__device__ int   g_csr_s[MAX_E];

__device__ __forceinline__ float leaky02(float z) {
    return z > 0.f ? z : 0.2f * z;
}

#define MMA_BF16(c, a, b) \
    asm volatile("mma.sync.aligned.m16n8k16.row.col.f32.bf16.bf16.f32 " \
        "{%0,%1,%2,%3},{%4,%5,%6,%7},{%8,%9},{%0,%1,%2,%3};" \
        : "+f"((c)[0]), "+f"((c)[1]), "+f"((c)[2]), "+f"((c)[3]) \
        : "r"((a)[0]), "r"((a)[1]), "r"((a)[2]), "r"((a)[3]), \
          "r"((b)[0]), "r"((b)[1]))

#define LDM_X4(r, addr) \
    asm volatile("ldmatrix.sync.aligned.m8n8.x4.shared.b16 {%0,%1,%2,%3}, [%4];" \
        : "=r"((r)[0]), "=r"((r)[1]), "=r"((r)[2]), "=r"((r)[3]) : "r"(addr))

#define LDM_X4T(r, addr) \
    asm volatile("ldmatrix.sync.aligned.m8n8.x4.trans.shared.b16 {%0,%1,%2,%3}, [%4];" \
        : "=r"((r)[0]), "=r"((r)[1]), "=r"((r)[2]), "=r"((r)[3]) : "r"(addr))

__device__ __forceinline__ uint32_t smem_u32(const void* p) {
    uint32_t a;
    asm("{ .reg .u64 t; cvta.to.shared.u64 t, %1; cvt.u32.u64 %0, t; }"
        : "=r"(a) : "l"(p));
    return a;
}

// split (x,y) into packed bf16 hi pair and lo pair
__device__ __forceinline__ void split2(float x, float y,
                                       uint32_t& h, uint32_t& l) {
    __nv_bfloat162 hh = __floats2bfloat162_rn(x, y);
    float rx = __bfloat162float(hh.x), ry = __bfloat162float(hh.y);
    __nv_bfloat162 ll = __floats2bfloat162_rn(x - rx, y - ry);
    h = *(uint32_t*)&hh;
    l = *(uint32_t*)&ll;
}

// ---------------- fold
__global__ void fold_kernel(const float* __restrict__ W_dst,
                            const float* __restrict__ att_dst) {
    int k = threadIdx.x;
    #pragma unroll
    for (int h = 0; h < HEADS; h++) {
        float s = 0.f;
        #pragma unroll 8
        for (int d = 0; d < 32; d++)
            s += W_dst[k * FDIM + h * 32 + d] * att_dst[h * 32 + d];
        g_fold_v[k * HEADS + h] = s;
    }
}

// ---------------- CSR build (unchanged, verified) ----------------
__global__ void zero_deg_kernel(int n) {
    int i = blockIdx.x * blockDim.x + threadIdx.x;
    if (i < n) g_deg[i] = 0;
}

__global__ void hist_kernel(const int* __restrict__ ed, int E) {
    int e = blockIdx.x * blockDim.x + threadIdx.x;
    if (e < E) atomicAdd(&g_deg[ed[e]], 1);
}

__global__ __launch_bounds__(256)
void scan_local_kernel(int n) {
    __shared__ int warp_tot[8];
    int t = threadIdx.x;
    int lane = t & 31, w = t >> 5;
    int base = blockIdx.x * SCAN_TILE + t * 4;

    int4 v = make_int4(0, 0, 0, 0);
    if (base + 3 < n) {
        v = *(const int4*)(g_deg + base);
    } else if (base < n) {
        v.x = g_deg[base];
        if (base + 1 < n) v.y = g_deg[base + 1];
        if (base + 2 < n) v.z = g_deg[base + 2];
    }
    int tot = v.x + v.y + v.z + v.w;

    int inc = tot;
    #pragma unroll
    for (int off = 1; off < 32; off <<= 1) {
        int x = __shfl_up_sync(0xffffffffu, inc, off);
        if (lane >= off) inc += x;
    }
    if (lane == 31) warp_tot[w] = inc;
    __syncthreads();
    if (t < 8) {
        int x = warp_tot[t];
        #pragma unroll
        for (int off = 1; off < 8; off <<= 1) {
            int y = __shfl_up_sync(0xffu, x, off);
            if (t >= off) x += y;
        }
        warp_tot[t] = x;
    }
    __syncthreads();

    int excl = (w > 0 ? warp_tot[w - 1] : 0) + (inc - tot);
    if (base < n) {
        g_row[base] = excl;
        if (base + 1 < n) g_row[base + 1] = excl + v.x;
        if (base + 2 < n) g_row[base + 2] = excl + v.x + v.y;
        if (base + 3 < n) g_row[base + 3] = excl + v.x + v.y + v.z;
    }
    if (t == 0) g_bsum[blockIdx.x] = warp_tot[7];
}

__global__ __launch_bounds__(256)
void scan_bsum_kernel(int nb, int n) {
    __shared__ int s[256];
    int t = threadIdx.x;
    s[t] = (t < nb) ? g_bsum[t] : 0;
    __syncthreads();
    #pragma unroll
    for (int off = 1; off < 256; off <<= 1) {
        int v = (t >= off) ? s[t - off] : 0;
        __syncthreads();
        s[t] += v;
        __syncthreads();
    }
    if (t < nb) g_boff[t] = (t > 0) ? s[t - 1] : 0;
    if (t == 0) g_row[n] = s[255];
}

__global__ __launch_bounds__(256)
void scan_apply_kernel(int n) {
    int t = threadIdx.x;
    int base = blockIdx.x * SCAN_TILE + t * 4;
    int off = g_boff[blockIdx.x];
    #pragma unroll
    for (int j = 0; j < 4; j++) {
        int i = base + j;
        if (i < n) {
            int r = g_row[i] + off;
            g_row[i] = r;
            g_cursor[i] = r;
        }
    }
}

__global__ void scatter_kernel(const int* __restrict__ es,
                               const int* __restrict__ ed, int E) {
    int e = blockIdx.x * blockDim.x + threadIdx.x;
    if (e >= E) return;
    int pos = atomicAdd(&g_cursor[ed[e]], 1);
    g_csr_s[pos] = es[e];
}

// ---------------- aggregate (unchanged, verified)
__global__ __launch_bounds__(256)
void aggr_kernel(float* __restrict__ out, int n_dst) {
    int d = (blockIdx.x * blockDim.x + threadIdx.x) >> 5;
    int lane = threadIdx.x & 31;
    if (d >= n_dst) return;
    int h = lane >> 3;

    int i   = g_row[d];
    int end = g_row[d + 1];
    float adv = g_adst[d * HEADS + h];

    float4 acc = make_float4(0.f, 0.f, 0.f, 0.f);
    float wsum = 0.f;
    const float4* feat4 = (const float4*)g_feat;

    int   s_cur = (i < end) ? g_csr_s[i] : 0;
    float a_cur = (i < end) ? g_asrc[s_cur * HEADS + h] : 0.f;
    for (; i < end; ) {
        int inext = i + 1;
        int   s_nxt = 0;
        float a_nxt = 0.f;
        if (inext < end) {
            s_nxt = g_csr_s[inext];
            a_nxt = g_asrc[s_nxt * HEADS + h];
        }
        float w = __expf(leaky02(a_cur + adv));
        float4 f = feat4[s_cur * 32 + lane];
        acc.x += w * f.x; acc.y += w * f.y;
        acc.z += w * f.z; acc.w += w * f.w;
        wsum += w;
        s_cur = s_nxt; a_cur = a_nxt;
        i = inext;
    }

    float rs = 1.f / (wsum + 1e-16f);
    float4* out4 = (float4*)out;
    float4 o = out4[d * 32 + lane];
    o.x += acc.x * rs; o.y += acc.y * rs;
    o.z += acc.z * rs; o.w += acc.w * rs;
    out4[d * 32 + lane] = o;
}

// ================== mma.sync GEMM v2 (ldmatrix-fed) =========================
// A tiles [m][k] bf16 hi/lo; B tiles [k][n] bf16 hi/lo (no transpose; ldmatrix
// .trans supplies the col-major fragment). 8 warps: wm = wid&1, wn = wid>>1.
#define KS 136   // padded row stride in bf16: 272B -> conflict-free ldmatrix
#define TILE_BF16 (128 * KS)
#define SM_GEMM_BYTES (4 * TILE_BF16 * 2 + 640 * 4)

template <int MODE>
__global__ __launch_bounds__(256, 1)
void gemm_mma_kernel(const float* __restrict__ A,
                     const float* __restrict__ W,     // [K=128, N=128]
                     const float* __restrict__ aux,   // att_src (M0) / bias (M1)
                     float* __restrict__ C,
                     float* __restrict__ alpha_out,
                     int nrows) {
    extern __shared__ char smem[];
    __nv_bfloat16* Ah = (__nv_bfloat16*)smem;
    __nv_bfloat16* Al = Ah + TILE_BF16;
    __nv_bfloat16* Bh = Al + TILE_BF16;
    __nv_bfloat16* Bl = Bh + TILE_BF16;
    float* xtra = (float*)(Bl + TILE_BF16);   // [0:128) att/bias, [128:640) fold

    int tid = threadIdx.x;
    int wid = tid >> 5, lane = tid & 31;
    int m0 = blockIdx.x * 128;

    if (tid < FDIM) xtra[tid] = aux[tid];
    if (MODE == 1) {
        for (int i = tid; i < FDIM * HEADS; i += 256) xtra[128 + i] = g_fold_v[i];
    }

    // A staging: [m][k], float4 loads, uint2 stores (hi and lo)
    const float4 zero4 = make_float4(0.f, 0.f, 0.f, 0.f);
    for (int idx = tid; idx < 128 * 32; idx += 256) {
        int row = idx >> 5, c4 = (idx & 31) * 4;
        int grow = m0 + row;
        float4 v = (grow < nrows) ? *(const float4*)(A + (size_t)grow * FDIM + c4)
                                  : zero4;
        uint32_t h01, l01, h23, l23;
        split2(v.x, v.y, h01, l01);
        split2(v.z, v.w, h23, l23);
        *(uint2*)(Ah + row * KS + c4) = make_uint2(h01, h23);
        *(uint2*)(Al + row * KS + c4) = make_uint2(l01, l23);
    }
    // B staging: [k][n] directly from W (coalesced, no transpose)
    for (int idx = tid; idx < 128 * 32; idx += 256) {
        int k = idx >> 5, n4 = (idx & 31) * 4;
        float4 v = *(const float4*)(W + (size_t)k * FDIM + n4);
        uint32_t h01, l01, h23, l23;
        split2(v.x, v.y, h01, l01);
        split2(v.z, v.w, h23, l23);
        *(uint2*)(Bh + k * KS + n4) = make_uint2(h01, h23);
        *(uint2*)(Bl + k * KS + n4) = make_uint2(l01, l23);
    }
    __syncthreads();

    int wm = wid & 1, wn = wid >> 1;
    int g = lane >> 2, q = lane & 3;

    // per-lane ldmatrix base addresses
    uint32_t ah_b = smem_u32(Ah), al_b = smem_u32(Al);
    uint32_t bh_b = smem_u32(Bh), bl_b = smem_u32(Bl);
    uint32_t a_off = (uint32_t)(((wm * 64 + (lane & 15)) * KS
                                 + ((lane >> 4) << 3)) * 2);
    uint32_t b_off = (uint32_t)(((lane & 15) * KS
                                 + wn * 32 + ((lane >> 4) << 3)) * 2);

    float c[4][4][4];
    #pragma unroll
    for (int mf = 0; mf < 4; mf++)
        #pragma unroll
        for (int nf = 0; nf < 4; nf++)
            #pragma unroll
            for (int r = 0; r < 4; r++) c[mf][nf][r] = 0.f;

    #pragma unroll
    for (int kb8 = 0; kb8 < 8; kb8++) {
        int kb = kb8 * 16;
        uint32_t ah[4][4], al[4][4], bh[2][4], bl[2][4];
        #pragma unroll
        for (int mf = 0; mf < 4; mf++) {
            uint32_t off = a_off + (uint32_t)((mf * 16 * KS + kb) * 2);
            LDM_X4(ah[mf], ah_b + off);
            LDM_X4(al[mf], al_b + off);
        }
        #pragma unroll
        for (int p = 0; p < 2; p++) {
            uint32_t off = b_off + (uint32_t)((kb * KS + p * 16) * 2);
            LDM_X4T(bh[p], bh_b + off);
            LDM_X4T(bl[p], bl_b + off);
        }
        #pragma unroll
        for (int mf = 0; mf < 4; mf++)
            #pragma unroll
            for (int nf = 0; nf < 4; nf++) {
                uint32_t* ph = &bh[nf >> 1][(nf & 1) * 2];
                uint32_t* pl = &bl[nf >> 1][(nf & 1) * 2];
                MMA_BF16(c[mf][nf], ah[mf], ph);
                MMA_BF16(c[mf][nf], ah[mf], pl);
                MMA_BF16(c[mf][nf], al[mf], ph);
            }
    }

    // epilogue: store C (+bias for MODE 1)
    #pragma unroll
    for (int mf = 0; mf < 4; mf++) {
        int row0 = m0 + wm * 64 + mf * 16 + g;
        #pragma unroll
        for (int nf = 0; nf < 4; nf++) {
            int col = wn * 32 + nf * 8 + q * 2;
            float v0 = c[mf][nf][0], v1 = c[mf][nf][1];
            float v2 = c[mf][nf][2], v3 = c[mf][nf][3];
            if (MODE == 1) {
                v0 += xtra[col]; v1 += xtra[col + 1];
                v2 += xtra[col]; v3 += xtra[col + 1];
            }
            if (row0 < nrows)
                *(float2*)(C + (size_t)row0 * FDIM + col) = make_float2(v0, v1);
            if (row0 + 8 < nrows)
                *(float2*)(C + (size_t)(row0 + 8) * FDIM + col) = make_float2(v2, v3);
        }
    }

    if (MODE == 0) {
        int h = wn;
        #pragma unroll
        for (int mf = 0; mf < 4; mf++) {
            float p0 = 0.f, p1 = 0.f;
            #pragma unroll
            for (int nf = 0; nf < 4; nf++) {
                int col = wn * 32 + nf * 8 + q * 2;
                p0 += c[mf][nf][0] * xtra[col] + c[mf][nf][1] * xtra[col + 1];
                p1 += c[mf][nf][2] * xtra[col] + c[mf][nf][3] * xtra[col + 1];
            }
            p0 += __shfl_xor_sync(0xffffffffu, p0, 1);
            p0 += __shfl_xor_sync(0xffffffffu, p0, 2);
            p1 += __shfl_xor_sync(0xffffffffu, p1, 1);
            p1 += __shfl_xor_sync(0xffffffffu, p1, 2);
            if (q == 0) {
                int row0 = m0 + wm * 64 + mf * 16 + g;
                if (row0 < nrows)     alpha_out[row0 * HEADS + h] = p0;
                if (row0 + 8 < nrows) alpha_out[(row0 + 8) * HEADS + h] = p1;
            }
        }
    } else {
        // alpha_dst = x @ fold_v, x recovered from hi+lo SMEM (uint32 pairs)
        if (tid < 128) {
            int row = tid;
            int grow = m0 + row;
            if (grow < nrows) {
                float a0 = 0.f, a1 = 0.f, a2 = 0.f, a3 = 0.f;
                const uint32_t* ph = (const uint32_t*)(Ah + row * KS);
                const uint32_t* pl = (const uint32_t*)(Al + row * KS);
                for (int k2 = 0; k2 < 64; k2++) {
                    uint32_t hw = ph[k2], lw = pl[k2];
                    __nv_bfloat162 hb = *(__nv_bfloat162*)&hw;
                    __nv_bfloat162 lb = *(__nv_bfloat162*)&lw;
                    float x0 = __bfloat162float(hb.x) + __bfloat162float(lb.x);
                    float x1 = __bfloat162float(hb.y) + __bfloat162float(lb.y);
                    int k = k2 * 2;
                    a0 += x0 * xtra[128 + k * 4 + 0] + x1 * xtra[128 + k * 4 + 4];
                    a1 += x0 * xtra[128 + k * 4 + 1] + x1 * xtra[128 + k * 4 + 5];
                    a2 += x0 * xtra[128 + k * 4 + 2] + x1 * xtra[128 + k * 4 + 6];
                    a3 += x0 * xtra[128 + k * 4 + 3] + x1 * xtra[128 + k * 4 + 7];
                }
                ((float4*)alpha_out)[grow] = make_float4(a0, a1, a2, a3);
            }
        }
    }
}

// ---------------------------------------------------------------------------
extern "C" void kernel_launch(void* const* d_in, const int* in_sizes, int n_in,
                              void* d_out, int out_size) {
    const float* x_src    = (const float*)d_in[0];
    const float* x_dst    = (const float*)d_in[1];
    const int*   edge_src = (const int*)d_in[2];
    const int*   edge_dst = (const int*)d_in[3];
    int off = (n_in >= 11) ? 5 : 4;
    const float* W_src   = (const float*)d_in[off + 0];
    const float* W_dst   = (const float*)d_in[off + 1];
    const float* att_src = (const float*)d_in[off + 2];
    const float* att_dst = (const float*)d_in[off + 3];
    const float* W_self  = (const float*)d_in[off + 4];
    const float* b_self  = (const float*)d_in[off + 5];
    float* out = (float*)d_out;

    int n_src = in_sizes[0] / FDIM;
    int n_dst = in_sizes[1] / FDIM;
    int E     = in_sizes[2];

    static float* p_feat = nullptr;
    static float* p_asrc = nullptr;
    static float* p_adst = nullptr;
    static cudaStream_t s1 = nullptr, s2 = nullptr;
    static cudaEvent_t ev_fork = nullptr, ev_g1 = nullptr, ev_csr = nullptr;
    if (!p_feat) {
        cudaGetSymbolAddress((void**)&p_feat, g_feat);
        cudaGetSymbolAddress((void**)&p_asrc, g_asrc);
        cudaGetSymbolAddress((void**)&p_adst, g_adst);
        cudaStreamCreateWithFlags(&s1, cudaStreamNonBlocking);
        cudaStreamCreateWithFlags(&s2, cudaStreamNonBlocking);
        cudaEventCreateWithFlags(&ev_fork, cudaEventDisableTiming);
        cudaEventCreateWithFlags(&ev_g1,   cudaEventDisableTiming);
        cudaEventCreateWithFlags(&ev_csr,  cudaEventDisableTiming);
        cudaFuncSetAttribute(gemm_mma_kernel<0>,
            cudaFuncAttributeMaxDynamicSharedMemorySize, SM_GEMM_BYTES);
        cudaFuncSetAttribute(gemm_mma_kernel<1>,
            cudaFuncAttributeMaxDynamicSharedMemorySize, SM_GEMM_BYTES);
    }

    int nb = (n_dst + SCAN_TILE - 1) / SCAN_TILE;

    // main: fold (needed by gemm<1>)
    fold_kernel<<<1, 128>>>(W_dst, att_dst);

    cudaEventRecord(ev_fork, 0);
    cudaStreamWaitEvent(s1, ev_fork, 0);
    cudaStreamWaitEvent(s2, ev_fork, 0);

    // s2: CSR build
    zero_deg_kernel<<<(n_dst + 255) / 256, 256, 0, s2>>>(n_dst);
    hist_kernel<<<(E + 255) / 256, 256, 0, s2>>>(edge_dst, E);
    scan_local_kernel<<<nb, 256, 0, s2>>>(n_dst);
    scan_bsum_kernel<<<1, 256, 0, s2>>>(nb, n_dst);
    scan_apply_kernel<<<nb, 256, 0, s2>>>(n_dst);
    scatter_kernel<<<(E + 255) / 256, 256, 0, s2>>>(edge_src, edge_dst, E);
    cudaEventRecord(ev_csr, s2);

    // s1: dst GEMM (out self-term + alpha_dst)
    gemm_mma_kernel<1><<<(n_dst + 127) / 128, 256, SM_GEMM_BYTES, s1>>>(
        x_dst, W_self, b_self, out, p_adst, n_dst);
    cudaEventRecord(ev_g1, s1);

    // main: src GEMM (feat + alpha_src)
    gemm_mma_kernel<0><<<(n_src + 127) / 128, 256, SM_GEMM_BYTES>>>(
        x_src, W_src, att_src, p_feat, p_asrc, n_src);

    // join
    cudaStreamWaitEvent(0, ev_g1, 0);
    cudaStreamWaitEvent(0, ev_csr, 0);
    long long total_threads = (long long)n_dst * 32;
    int blocks = (int)((total_threads + 255) / 256);
    aggr_kernel<<<blocks, 256>>>(out, n_dst);
}

// round 12
// speedup vs baseline: 1.1025x; 1.0396x over previous
#include <cuda_runtime.h>
#include <cuda_bf16.h>
#include <cstdint>

// ---------------------------------------------------------------------------
// BipartiteGATConv — round 12: heterogeneous-pipe GEMM overlap.
//   gemm<0> (src -> feat + alpha_src): HMMA mma.sync (tensor pipe)  [round-11]
//   gemm<1> (dst -> out  + alpha_dst): FFMA2 f32x2    (fma pipe)    [round-8]
// Run concurrently on separate streams; one CTA of each co-resides per SM
// (168KB smem, ~58K regs, 16 warps). CSR/aggr/launcher otherwise identical.
// ---------------------------------------------------------------------------

#define MAX_N   50000
#define MAX_E   800000
#define FDIM    128
#define HEADS   4
#define SCAN_TILE 1024
#define MAX_SB  ((MAX_N + SCAN_TILE - 1) / SCAN_TILE)

__device__ __align__(16) float g_feat[MAX_N * FDIM];
__device__ __align__(16) float g_asrc[MAX_N * HEADS];
__device__ __align__(16) float g_adst[MAX_N * HEADS];
__device__ __align__(16) float g_fold_v[FDIM * HEADS];
__device__ __align__(16) int   g_deg[MAX_N];
__device__ int   g_row[MAX_N + 1];
__device__ int   g_cursor[MAX_N];
__device__ int   g_bsum[MAX_SB];
__device__ int   g_boff[MAX_SB];
__device__ int   g_csr_s[MAX_E];

typedef unsigned long long u64;

__device__ __forceinline__ float leaky02(float z) {
    return z > 0.f ? z : 0.2f * z;
}

// ---- FFMA2 helpers
#define FMA_F32X2(d, a, b, c) \
    asm("fma.rn.f32x2 %0, %1, %2, %3;" : "=l"(d) : "l"(a), "l"(b), "l"(c))
#define PACK_DUP_F32X2(d, s) \
    asm("mov.b64 %0, {%1, %1};" : "=l"(d) : "r"(__float_as_uint(s)))
#define UNPACK_F32X2(lo, hi, in) \
    asm("mov.b64 {%0, %1}, %2;" : "=r"(lo), "=r"(hi) : "l"(in))

// ---- HMMA helpers
#define MMA_BF16(c, a, b) \
    asm volatile("mma.sync.aligned.m16n8k16.row.col.f32.bf16.bf16.f32 " \
        "{%0,%1,%2,%3},{%4,%5,%6,%7},{%8,%9},{%0,%1,%2,%3};" \
        : "+f"((c)[0]), "+f"((c)[1]), "+f"((c)[2]), "+f"((c)[3]) \
        : "r"((a)[0]), "r"((a)[1]), "r"((a)[2]), "r"((a)[3]), \
          "r"((b)[0]), "r"((b)[1]))
#define LDM_X4(r, addr) \
    asm volatile("ldmatrix.sync.aligned.m8n8.x4.shared.b16 {%0,%1,%2,%3}, [%4];" \
        : "=r"((r)[0]), "=r"((r)[1]), "=r"((r)[2]), "=r"((r)[3]) : "r"(addr))
#define LDM_X4T(r, addr) \
    asm volatile("ldmatrix.sync.aligned.m8n8.x4.trans.shared.b16 {%0,%1,%2,%3}, [%4];" \
        : "=r"((r)[0]), "=r"((r)[1]), "=r"((r)[2]), "=r"((r)[3]) : "r"(addr))

__device__ __forceinline__ uint32_t smem_u32(const void* p) {
    uint32_t a;
    asm("{ .reg .u64 t; cvta.to.shared.u64 t, %1; cvt.u32.u64 %0, t; }"
        : "=r"(a) : "l"(p));
    return a;
}

__device__ __forceinline__ void split2(float x, float y,
                                       uint32_t& h, uint32_t& l) {
    __nv_bfloat162 hh = __floats2bfloat162_rn(x, y);
    float rx = __bfloat162float(hh.x), ry = __bfloat162float(hh.y);
    __nv_bfloat162 ll = __floats2bfloat162_rn(x - rx, y - ry);
    h = *(uint32_t*)&hh;
    l = *(uint32_t*)&ll;
}

// ---------------- fold
__global__ void fold_kernel(const float* __restrict__ W_dst,
                            const float* __restrict__ att_dst) {
    int k = threadIdx.x;
    #pragma unroll
    for (int h = 0; h < HEADS; h++) {
        float s = 0.f;
        #pragma unroll 8
        for (int d = 0; d < 32; d++)
            s += W_dst[k * FDIM + h * 32 + d] * att_dst[h * 32 + d];
        g_fold_v[k * HEADS + h] = s;
    }
}

// ---------------- CSR build (unchanged, verified) ----------------
__global__ void zero_deg_kernel(int n) {
    int i = blockIdx.x * blockDim.x + threadIdx.x;
    if (i < n) g_deg[i] = 0;
}

__global__ void hist_kernel(const int* __restrict__ ed, int E) {
    int e = blockIdx.x * blockDim.x + threadIdx.x;
    if (e < E) atomicAdd(&g_deg[ed[e]], 1);
}

__global__ __launch_bounds__(256)
void scan_local_kernel(int n) {
    __shared__ int warp_tot[8];
    int t = threadIdx.x;
    int lane = t & 31, w = t >> 5;
    int base = blockIdx.x * SCAN_TILE + t * 4;

    int4 v = make_int4(0, 0, 0, 0);
    if (base + 3 < n) {
        v = *(const int4*)(g_deg + base);
    } else if (base < n) {
        v.x = g_deg[base];
        if (base + 1 < n) v.y = g_deg[base + 1];
        if (base + 2 < n) v.z = g_deg[base + 2];
    }
    int tot = v.x + v.y + v.z + v.w;

    int inc = tot;
    #pragma unroll
    for (int off = 1; off < 32; off <<= 1) {
        int x = __shfl_up_sync(0xffffffffu, inc, off);
        if (lane >= off) inc += x;
    }
    if (lane == 31) warp_tot[w] = inc;
    __syncthreads();
    if (t < 8) {
        int x = warp_tot[t];
        #pragma unroll
        for (int off = 1; off < 8; off <<= 1) {
            int y = __shfl_up_sync(0xffu, x, off);
            if (t >= off) x += y;
        }
        warp_tot[t] = x;
    }
    __syncthreads();

    int excl = (w > 0 ? warp_tot[w - 1] : 0) + (inc - tot);
    if (base < n) {
        g_row[base] = excl;
        if (base + 1 < n) g_row[base + 1] = excl + v.x;
        if (base + 2 < n) g_row[base + 2] = excl + v.x + v.y;
        if (base + 3 < n) g_row[base + 3] = excl + v.x + v.y + v.z;
    }
    if (t == 0) g_bsum[blockIdx.x] = warp_tot[7];
}

__global__ __launch_bounds__(256)
void scan_bsum_kernel(int nb, int n) {
    __shared__ int s[256];
    int t = threadIdx.x;
    s[t] = (t < nb) ? g_bsum[t] : 0;
    __syncthreads();
    #pragma unroll
    for (int off = 1; off < 256; off <<= 1) {
        int v = (t >= off) ? s[t - off] : 0;
        __syncthreads();
        s[t] += v;
        __syncthreads();
    }
    if (t < nb) g_boff[t] = (t > 0) ? s[t - 1] : 0;
    if (t == 0) g_row[n] = s[255];
}

__global__ __launch_bounds__(256)
void scan_apply_kernel(int n) {
    int t = threadIdx.x;
    int base = blockIdx.x * SCAN_TILE + t * 4;
    int off = g_boff[blockIdx.x];
    #pragma unroll
    for (int j = 0; j < 4; j++) {
        int i = base + j;
        if (i < n) {
            int r = g_row[i] + off;
            g_row[i] = r;
            g_cursor[i] = r;
        }
    }
}

__global__ void scatter_kernel(const int* __restrict__ es,
                               const int* __restrict__ ed, int E) {
    int e = blockIdx.x * blockDim.x + threadIdx.x;
    if (e >= E) return;
    int pos = atomicAdd(&g_cursor[ed[e]], 1);
    g_csr_s[pos] = es[e];
}

// ---------------- aggregate (unchanged, verified)
__global__ __launch_bounds__(256)
void aggr_kernel(float* __restrict__ out, int n_dst) {
    int d = (blockIdx.x * blockDim.x + threadIdx.x) >> 5;
    int lane = threadIdx.x & 31;
    if (d >= n_dst) return;
    int h = lane >> 3;

    int i   = g_row[d];
    int end = g_row[d + 1];
    float adv = g_adst[d * HEADS + h];

    float4 acc = make_float4(0.f, 0.f, 0.f, 0.f);
    float wsum = 0.f;
    const float4* feat4 = (const float4*)g_feat;

    int   s_cur = (i < end) ? g_csr_s[i] : 0;
    float a_cur = (i < end) ? g_asrc[s_cur * HEADS + h] : 0.f;
    for (; i < end; ) {
        int inext = i + 1;
        int   s_nxt = 0;
        float a_nxt = 0.f;
        if (inext < end) {
            s_nxt = g_csr_s[inext];
            a_nxt = g_asrc[s_nxt * HEADS + h];
        }
        float w = __expf(leaky02(a_cur + adv));
        float4 f = feat4[s_cur * 32 + lane];
        acc.x += w * f.x; acc.y += w * f.y;
        acc.z += w * f.z; acc.w += w * f.w;
        wsum += w;
        s_cur = s_nxt; a_cur = a_nxt;
        i = inext;
    }

    float rs = 1.f / (wsum + 1e-16f);
    float4* out4 = (float4*)out;
    float4 o = out4[d * 32 + lane];
    o.x += acc.x * rs; o.y += acc.y * rs;
    o.z += acc.z * rs; o.w += acc.w * rs;
    out4[d * 32 + lane] = o;
}

// ============ HMMA GEMM (src): C=feat, alpha_src from frags (round-11) =====
#define KS 136
#define TILE_BF16 (128 * KS)
#define SM_GEMM_BYTES (4 * TILE_BF16 * 2 + 640 * 4)

__global__ __launch_bounds__(256, 1)
void gemm_src_hmma(const float* __restrict__ A,
                   const float* __restrict__ W,     // [K=128, N=128]
                   const float* __restrict__ aux,   // att_src
                   float* __restrict__ C,
                   float* __restrict__ alpha_out,
                   int nrows) {
    extern __shared__ char smem[];
    __nv_bfloat16* Ah = (__nv_bfloat16*)smem;
    __nv_bfloat16* Al = Ah + TILE_BF16;
    __nv_bfloat16* Bh = Al + TILE_BF16;
    __nv_bfloat16* Bl = Bh + TILE_BF16;
    float* xtra = (float*)(Bl + TILE_BF16);

    int tid = threadIdx.x;
    int wid = tid >> 5, lane = tid & 31;
    int m0 = blockIdx.x * 128;

    if (tid < FDIM) xtra[tid] = aux[tid];

    const float4 zero4 = make_float4(0.f, 0.f, 0.f, 0.f);
    for (int idx = tid; idx < 128 * 32; idx += 256) {
        int row = idx >> 5, c4 = (idx & 31) * 4;
        int grow = m0 + row;
        float4 v = (grow < nrows) ? *(const float4*)(A + (size_t)grow * FDIM + c4)
                                  : zero4;
        uint32_t h01, l01, h23, l23;
        split2(v.x, v.y, h01, l01);
        split2(v.z, v.w, h23, l23);
        *(uint2*)(Ah + row * KS + c4) = make_uint2(h01, h23);
        *(uint2*)(Al + row * KS + c4) = make_uint2(l01, l23);
    }
    for (int idx = tid; idx < 128 * 32; idx += 256) {
        int k = idx >> 5, n4 = (idx & 31) * 4;
        float4 v = *(const float4*)(W + (size_t)k * FDIM + n4);
        uint32_t h01, l01, h23, l23;
        split2(v.x, v.y, h01, l01);
        split2(v.z, v.w, h23, l23);
        *(uint2*)(Bh + k * KS + n4) = make_uint2(h01, h23);
        *(uint2*)(Bl + k * KS + n4) = make_uint2(l01, l23);
    }
    __syncthreads();

    int wm = wid & 1, wn = wid >> 1;
    int g = lane >> 2, q = lane & 3;

    uint32_t ah_b = smem_u32(Ah), al_b = smem_u32(Al);
    uint32_t bh_b = smem_u32(Bh), bl_b = smem_u32(Bl);
    uint32_t a_off = (uint32_t)(((wm * 64 + (lane & 15)) * KS
                                 + ((lane >> 4) << 3)) * 2);
    uint32_t b_off = (uint32_t)(((lane & 15) * KS
                                 + wn * 32 + ((lane >> 4) << 3)) * 2);

    float c[4][4][4];
    #pragma unroll
    for (int mf = 0; mf < 4; mf++)
        #pragma unroll
        for (int nf = 0; nf < 4; nf++)
            #pragma unroll
            for (int r = 0; r < 4; r++) c[mf][nf][r] = 0.f;

    #pragma unroll
    for (int kb8 = 0; kb8 < 8; kb8++) {
        int kb = kb8 * 16;
        uint32_t ah[4][4], al[4][4], bh[2][4], bl[2][4];
        #pragma unroll
        for (int mf = 0; mf < 4; mf++) {
            uint32_t off = a_off + (uint32_t)((mf * 16 * KS + kb) * 2);
            LDM_X4(ah[mf], ah_b + off);
            LDM_X4(al[mf], al_b + off);
        }
        #pragma unroll
        for (int p = 0; p < 2; p++) {
            uint32_t off = b_off + (uint32_t)((kb * KS + p * 16) * 2);
            LDM_X4T(bh[p], bh_b + off);
            LDM_X4T(bl[p], bl_b + off);
        }
        #pragma unroll
        for (int mf = 0; mf < 4; mf++)
            #pragma unroll
            for (int nf = 0; nf < 4; nf++) {
                uint32_t* ph = &bh[nf >> 1][(nf & 1) * 2];
                uint32_t* pl = &bl[nf >> 1][(nf & 1) * 2];
                MMA_BF16(c[mf][nf], ah[mf], ph);
                MMA_BF16(c[mf][nf], ah[mf], pl);
                MMA_BF16(c[mf][nf], al[mf], ph);
            }
    }

    #pragma unroll
    for (int mf = 0; mf < 4; mf++) {
        int row0 = m0 + wm * 64 + mf * 16 + g;
        #pragma unroll
        for (int nf = 0; nf < 4; nf++) {
            int col = wn * 32 + nf * 8 + q * 2;
            if (row0 < nrows)
                *(float2*)(C + (size_t)row0 * FDIM + col) =
                    make_float2(c[mf][nf][0], c[mf][nf][1]);
            if (row0 + 8 < nrows)
                *(float2*)(C + (size_t)(row0 + 8) * FDIM + col) =
                    make_float2(c[mf][nf][2], c[mf][nf][3]);
        }
    }

    int h = wn;
    #pragma unroll
    for (int mf = 0; mf < 4; mf++) {
        float p0 = 0.f, p1 = 0.f;
        #pragma unroll
        for (int nf = 0; nf < 4; nf++) {
            int col = wn * 32 + nf * 8 + q * 2;
            p0 += c[mf][nf][0] * xtra[col] + c[mf][nf][1] * xtra[col + 1];
            p1 += c[mf][nf][2] * xtra[col] + c[mf][nf][3] * xtra[col + 1];
        }
        p0 += __shfl_xor_sync(0xffffffffu, p0, 1);
        p0 += __shfl_xor_sync(0xffffffffu, p0, 2);
        p1 += __shfl_xor_sync(0xffffffffu, p1, 1);
        p1 += __shfl_xor_sync(0xffffffffu, p1, 2);
        if (q == 0) {
            int row0 = m0 + wm * 64 + mf * 16 + g;
            if (row0 < nrows)     alpha_out[row0 * HEADS + h] = p0;
            if (row0 + 8 < nrows) alpha_out[(row0 + 8) * HEADS + h] = p1;
        }
    }
}

// ============ FFMA2 GEMM (dst): C=out+bias, alpha_dst in mainloop (round-8) =
#define BM 128
#define BN 128
#define BK 16
#define TM 8
#define TN 8

__global__ __launch_bounds__(256, 2)
void gemm_dst_ffma2(const float* __restrict__ A,
                    const float* __restrict__ B,
                    const float* __restrict__ aux,   // bias
                    float* __restrict__ C,
                    float* __restrict__ alpha_out,
                    int nrows) {
    __shared__ float As[2][BK][BM];
    __shared__ __align__(16) float Bs[2][BK][BN];
    __shared__ float xtra[FDIM * HEADS];

    int tid = threadIdx.x;
    int tn_idx = tid & 15;
    int tm_idx = tid >> 4;
    int tm0 = tm_idx * TM;
    int tn0 = tn_idx * TN;
    int m0 = blockIdx.x * BM;

    xtra[tid] = g_fold_v[tid];
    xtra[tid + 256] = g_fold_v[tid + 256];

    u64 acc2[TM][TN / 2];
    #pragma unroll
    for (int i = 0; i < TM; i++)
        #pragma unroll
        for (int j = 0; j < TN / 2; j++) acc2[i][j] = 0ull;

    int af_row[2], af_k4[2];
    int bf_k[2], bf_n4[2];
    #pragma unroll
    for (int i = 0; i < 2; i++) {
        int f = tid + i * 256;
        af_row[i] = f >> 2;
        af_k4[i]  = (f & 3) * 4;
        bf_k[i]   = f >> 5;
        bf_n4[i]  = (f & 31) * 4;
    }

    float4 a_reg[2], b_reg[2];
    const float4 zero4 = make_float4(0.f, 0.f, 0.f, 0.f);

    #pragma unroll
    for (int i = 0; i < 2; i++) {
        int grow = m0 + af_row[i];
        a_reg[i] = (grow < nrows)
            ? *(const float4*)(A + (size_t)grow * FDIM + af_k4[i]) : zero4;
        b_reg[i] = *(const float4*)(B + (size_t)bf_k[i] * FDIM + bf_n4[i]);
    }
    #pragma unroll
    for (int i = 0; i < 2; i++) {
        As[0][af_k4[i] + 0][af_row[i]] = a_reg[i].x;
        As[0][af_k4[i] + 1][af_row[i]] = a_reg[i].y;
        As[0][af_k4[i] + 2][af_row[i]] = a_reg[i].z;
        As[0][af_k4[i] + 3][af_row[i]] = a_reg[i].w;
        *(float4*)&Bs[0][bf_k[i]][bf_n4[i]] = b_reg[i];
    }
    __syncthreads();

    int h  = tn_idx >> 2;
    int qq = (tn_idx & 3) * 2;
    float av0 = 0.f, av1 = 0.f;

    int buf = 0;
    const int NT = FDIM / BK;
    for (int t = 0; t < NT; t++) {
        if (t + 1 < NT) {
            int kt = (t + 1) * BK;
            #pragma unroll
            for (int i = 0; i < 2; i++) {
                int grow = m0 + af_row[i];
                a_reg[i] = (grow < nrows)
                    ? *(const float4*)(A + (size_t)grow * FDIM + kt + af_k4[i]) : zero4;
                b_reg[i] = *(const float4*)(B + (size_t)(kt + bf_k[i]) * FDIM + bf_n4[i]);
            }
        }

        #pragma unroll
        for (int k = 0; k < BK; k++) {
            float4 a0 = *(const float4*)&As[buf][k][tm0];
            float4 a1 = *(const float4*)&As[buf][k][tm0 + 4];
            ulonglong2 bq0 = *(const ulonglong2*)&Bs[buf][k][tn0];
            ulonglong2 bq1 = *(const ulonglong2*)&Bs[buf][k][tn0 + 4];
            u64 bp[4] = {bq0.x, bq0.y, bq1.x, bq1.y};
            float avv[TM] = {a0.x, a0.y, a0.z, a0.w, a1.x, a1.y, a1.z, a1.w};
            #pragma unroll
            for (int i = 0; i < TM; i++) {
                u64 ad;
                PACK_DUP_F32X2(ad, avv[i]);
                #pragma unroll
                for (int j = 0; j < TN / 2; j++)
                    FMA_F32X2(acc2[i][j], ad, bp[j], acc2[i][j]);
            }
            float vv = xtra[(t * BK + k) * HEADS + h];
            av0 += As[buf][k][tm0 + qq]     * vv;
            av1 += As[buf][k][tm0 + qq + 1] * vv;
        }

        if (t + 1 < NT) {
            int nb = buf ^ 1;
            #pragma unroll
            for (int i = 0; i < 2; i++) {
                As[nb][af_k4[i] + 0][af_row[i]] = a_reg[i].x;
                As[nb][af_k4[i] + 1][af_row[i]] = a_reg[i].y;
                As[nb][af_k4[i] + 2][af_row[i]] = a_reg[i].z;
                As[nb][af_k4[i] + 3][af_row[i]] = a_reg[i].w;
                *(float4*)&Bs[nb][bf_k[i]][bf_n4[i]] = b_reg[i];
            }
            __syncthreads();
            buf = nb;
        }
    }

    float acc[TM][TN];
    #pragma unroll
    for (int i = 0; i < TM; i++)
        #pragma unroll
        for (int j = 0; j < TN / 2; j++) {
            unsigned lo, hi;
            UNPACK_F32X2(lo, hi, acc2[i][j]);
            acc[i][2 * j]     = __uint_as_float(lo);
            acc[i][2 * j + 1] = __uint_as_float(hi);
        }

    float4 bb0 = *(const float4*)(aux + tn0);
    float4 bb1 = *(const float4*)(aux + tn0 + 4);
    #pragma unroll
    for (int i = 0; i < TM; i++) {
        int row = m0 + tm0 + i;
        if (row < nrows) {
            float4 o0 = make_float4(acc[i][0] + bb0.x, acc[i][1] + bb0.y,
                                    acc[i][2] + bb0.z, acc[i][3] + bb0.w);
            float4 o1 = make_float4(acc[i][4] + bb1.x, acc[i][5] + bb1.y,
                                    acc[i][6] + bb1.z, acc[i][7] + bb1.w);
            *(float4*)(C + (size_t)row * FDIM + tn0)     = o0;
            *(float4*)(C + (size_t)row * FDIM + tn0 + 4) = o1;
        }
    }

    int r0 = m0 + tm0 + qq;
    if (r0 < nrows)     alpha_out[r0 * HEADS + h]       = av0;
    if (r0 + 1 < nrows) alpha_out[(r0 + 1) * HEADS + h] = av1;
}

// ---------------------------------------------------------------------------
extern "C" void kernel_launch(void* const* d_in, const int* in_sizes, int n_in,
                              void* d_out, int out_size) {
    const float* x_src    = (const float*)d_in[0];
    const float* x_dst    = (const float*)d_in[1];
    const int*   edge_src = (const int*)d_in[2];
    const int*   edge_dst = (const int*)d_in[3];
    int off = (n_in >= 11) ? 5 : 4;
    const float* W_src   = (const float*)d_in[off + 0];
    const float* W_dst   = (const float*)d_in[off + 1];
    const float* att_src = (const float*)d_in[off + 2];
    const float* att_dst = (const float*)d_in[off + 3];
    const float* W_self  = (const float*)d_in[off + 4];
    const float* b_self  = (const float*)d_in[off + 5];
    float* out = (float*)d_out;

    int n_src = in_sizes[0] / FDIM;
    int n_dst = in_sizes[1] / FDIM;
    int E     = in_sizes[2];

    static float* p_feat = nullptr;
    static float* p_asrc = nullptr;
    static float* p_adst = nullptr;
    static cudaStream_t s1 = nullptr, s2 = nullptr;
    static cudaEvent_t ev_fork = nullptr, ev_g1 = nullptr, ev_csr = nullptr;
    if (!p_feat) {
        cudaGetSymbolAddress((void**)&p_feat, g_feat);
        cudaGetSymbolAddress((void**)&p_asrc, g_asrc);
        cudaGetSymbolAddress((void**)&p_adst, g_adst);
        cudaStreamCreateWithFlags(&s1, cudaStreamNonBlocking);
        cudaStreamCreateWithFlags(&s2, cudaStreamNonBlocking);
        cudaEventCreateWithFlags(&ev_fork, cudaEventDisableTiming);
        cudaEventCreateWithFlags(&ev_g1,   cudaEventDisableTiming);
        cudaEventCreateWithFlags(&ev_csr,  cudaEventDisableTiming);
        cudaFuncSetAttribute(gemm_src_hmma,
            cudaFuncAttributeMaxDynamicSharedMemorySize, SM_GEMM_BYTES);
    }

    int nb = (n_dst + SCAN_TILE - 1) / SCAN_TILE;

    // main: fold (needed by gemm_dst)
    fold_kernel<<<1, 128>>>(W_dst, att_dst);

    cudaEventRecord(ev_fork, 0);
    cudaStreamWaitEvent(s1, ev_fork, 0);
    cudaStreamWaitEvent(s2, ev_fork, 0);

    // s2: CSR build
    zero_deg_kernel<<<(n_dst + 255) / 256, 256, 0, s2>>>(n_dst);
    hist_kernel<<<(E + 255) / 256, 256, 0, s2>>>(edge_dst, E);
    scan_local_kernel<<<nb, 256, 0, s2>>>(n_dst);
    scan_bsum_kernel<<<1, 256, 0, s2>>>(nb, n_dst);
    scan_apply_kernel<<<nb, 256, 0, s2>>>(n_dst);
    scatter_kernel<<<(E + 255) / 256, 256, 0, s2>>>(edge_src, edge_dst, E);
    cudaEventRecord(ev_csr, s2);

    // s1: dst GEMM on the FMA pipe (FFMA2)
    gemm_dst_ffma2<<<(n_dst + BM - 1) / BM, 256, 0, s1>>>(
        x_dst, W_self, b_self, out, p_adst, n_dst);
    cudaEventRecord(ev_g1, s1);

    // main: src GEMM on the tensor pipe (HMMA)
    gemm_src_hmma<<<(n_src + 127) / 128, 256, SM_GEMM_BYTES>>>(
        x_src, W_src, att_src, p_feat, p_asrc, n_src);

    // join
    cudaStreamWaitEvent(0, ev_g1, 0);
    cudaStreamWaitEvent(0, ev_csr, 0);
    long long total_threads = (long long)n_dst * 32;
    int blocks = (int)((total_threads + 255) / 256);
    aggr_kernel<<<blocks, 256>>>(out, n_dst);
}

// round 13
// speedup vs baseline: 1.1800x; 1.0703x over previous
#include <cuda_runtime.h>
#include <cuda_bf16.h>
#include <cstdint>

// ---------------------------------------------------------------------------
// BipartiteGATConv — round 13: heterogeneous-pipe GEMM overlap, fixed shapes.
//   gemm_src (HMMA, tensor pipe): BM=64 -> 105KB smem -> occupancy 2
//   gemm_dst (FFMA2, fma pipe):   round-8 kernel, unchanged
// CSR build / aggr / stream fork-join identical to verified round 8/12.
// ---------------------------------------------------------------------------

#define MAX_N   50000
#define MAX_E   800000
#define FDIM    128
#define HEADS   4
#define SCAN_TILE 1024
#define MAX_SB  ((MAX_N + SCAN_TILE - 1) / SCAN_TILE)

__device__ __align__(16) float g_feat[MAX_N * FDIM];
__device__ __align__(16) float g_asrc[MAX_N * HEADS];
__device__ __align__(16) float g_adst[MAX_N * HEADS];
__device__ __align__(16) float g_fold_v[FDIM * HEADS];
__device__ __align__(16) int   g_deg[MAX_N];
__device__ int   g_row[MAX_N + 1];
__device__ int   g_cursor[MAX_N];
__device__ int   g_bsum[MAX_SB];
__device__ int   g_boff[MAX_SB];
__device__ int   g_csr_s[MAX_E];

typedef unsigned long long u64;

__device__ __forceinline__ float leaky02(float z) {
    return z > 0.f ? z : 0.2f * z;
}

// ---- FFMA2 helpers
#define FMA_F32X2(d, a, b, c) \
    asm("fma.rn.f32x2 %0, %1, %2, %3;" : "=l"(d) : "l"(a), "l"(b), "l"(c))
#define PACK_DUP_F32X2(d, s) \
    asm("mov.b64 %0, {%1, %1};" : "=l"(d) : "r"(__float_as_uint(s)))
#define UNPACK_F32X2(lo, hi, in) \
    asm("mov.b64 {%0, %1}, %2;" : "=r"(lo), "=r"(hi) : "l"(in))

// ---- HMMA helpers
#define MMA_BF16(c, a, b) \
    asm volatile("mma.sync.aligned.m16n8k16.row.col.f32.bf16.bf16.f32 " \
        "{%0,%1,%2,%3},{%4,%5,%6,%7},{%8,%9},{%0,%1,%2,%3};" \
        : "+f"((c)[0]), "+f"((c)[1]), "+f"((c)[2]), "+f"((c)[3]) \
        : "r"((a)[0]), "r"((a)[1]), "r"((a)[2]), "r"((a)[3]), \
          "r"((b)[0]), "r"((b)[1]))
#define LDM_X4(r, addr) \
    asm volatile("ldmatrix.sync.aligned.m8n8.x4.shared.b16 {%0,%1,%2,%3}, [%4];" \
        : "=r"((r)[0]), "=r"((r)[1]), "=r"((r)[2]), "=r"((r)[3]) : "r"(addr))
#define LDM_X4T(r, addr) \
    asm volatile("ldmatrix.sync.aligned.m8n8.x4.trans.shared.b16 {%0,%1,%2,%3}, [%4];" \
        : "=r"((r)[0]), "=r"((r)[1]), "=r"((r)[2]), "=r"((r)[3]) : "r"(addr))

__device__ __forceinline__ uint32_t smem_u32(const void* p) {
    uint32_t a;
    asm("{ .reg .u64 t; cvta.to.shared.u64 t, %1; cvt.u32.u64 %0, t; }"
        : "=r"(a) : "l"(p));
    return a;
}

__device__ __forceinline__ void split2(float x, float y,
                                       uint32_t& h, uint32_t& l) {
    __nv_bfloat162 hh = __floats2bfloat162_rn(x, y);
    float rx = __bfloat162float(hh.x), ry = __bfloat162float(hh.y);
    __nv_bfloat162 ll = __floats2bfloat162_rn(x - rx, y - ry);
    h = *(uint32_t*)&hh;
    l = *(uint32_t*)&ll;
}

// ---------------- fold
__global__ void fold_kernel(const float* __restrict__ W_dst,
                            const float* __restrict__ att_dst) {
    int k = threadIdx.x;
    #pragma unroll
    for (int h = 0; h < HEADS; h++) {
        float s = 0.f;
        #pragma unroll 8
        for (int d = 0; d < 32; d++)
            s += W_dst[k * FDIM + h * 32 + d] * att_dst[h * 32 + d];
        g_fold_v[k * HEADS + h] = s;
    }
}

// ---------------- CSR build (unchanged, verified) ----------------
__global__ void zero_deg_kernel(int n) {
    int i = blockIdx.x * blockDim.x + threadIdx.x;
    if (i < n) g_deg[i] = 0;
}

__global__ void hist_kernel(const int* __restrict__ ed, int E) {
    int e = blockIdx.x * blockDim.x + threadIdx.x;
    if (e < E) atomicAdd(&g_deg[ed[e]], 1);
}

__global__ __launch_bounds__(256)
void scan_local_kernel(int n) {
    __shared__ int warp_tot[8];
    int t = threadIdx.x;
    int lane = t & 31, w = t >> 5;
    int base = blockIdx.x * SCAN_TILE + t * 4;

    int4 v = make_int4(0, 0, 0, 0);
    if (base + 3 < n) {
        v = *(const int4*)(g_deg + base);
    } else if (base < n) {
        v.x = g_deg[base];
        if (base + 1 < n) v.y = g_deg[base + 1];
        if (base + 2 < n) v.z = g_deg[base + 2];
    }
    int tot = v.x + v.y + v.z + v.w;

    int inc = tot;
    #pragma unroll
    for (int off = 1; off < 32; off <<= 1) {
        int x = __shfl_up_sync(0xffffffffu, inc, off);
        if (lane >= off) inc += x;
    }
    if (lane == 31) warp_tot[w] = inc;
    __syncthreads();
    if (t < 8) {
        int x = warp_tot[t];
        #pragma unroll
        for (int off = 1; off < 8; off <<= 1) {
            int y = __shfl_up_sync(0xffu, x, off);
            if (t >= off) x += y;
        }
        warp_tot[t] = x;
    }
    __syncthreads();

    int excl = (w > 0 ? warp_tot[w - 1] : 0) + (inc - tot);
    if (base < n) {
        g_row[base] = excl;
        if (base + 1 < n) g_row[base + 1] = excl + v.x;
        if (base + 2 < n) g_row[base + 2] = excl + v.x + v.y;
        if (base + 3 < n) g_row[base + 3] = excl + v.x + v.y + v.z;
    }
    if (t == 0) g_bsum[blockIdx.x] = warp_tot[7];
}

__global__ __launch_bounds__(256)
void scan_bsum_kernel(int nb, int n) {
    __shared__ int s[256];
    int t = threadIdx.x;
    s[t] = (t < nb) ? g_bsum[t] : 0;
    __syncthreads();
    #pragma unroll
    for (int off = 1; off < 256; off <<= 1) {
        int v = (t >= off) ? s[t - off] : 0;
        __syncthreads();
        s[t] += v;
        __syncthreads();
    }
    if (t < nb) g_boff[t] = (t > 0) ? s[t - 1] : 0;
    if (t == 0) g_row[n] = s[255];
}

__global__ __launch_bounds__(256)
void scan_apply_kernel(int n) {
    int t = threadIdx.x;
    int base = blockIdx.x * SCAN_TILE + t * 4;
    int off = g_boff[blockIdx.x];
    #pragma unroll
    for (int j = 0; j < 4; j++) {
        int i = base + j;
        if (i < n) {
            int r = g_row[i] + off;
            g_row[i] = r;
            g_cursor[i] = r;
        }
    }
}

__global__ void scatter_kernel(const int* __restrict__ es,
                               const int* __restrict__ ed, int E) {
    int e = blockIdx.x * blockDim.x + threadIdx.x;
    if (e >= E) return;
    int pos = atomicAdd(&g_cursor[ed[e]], 1);
    g_csr_s[pos] = es[e];
}

// ---------------- aggregate (unchanged, verified)
__global__ __launch_bounds__(256)
void aggr_kernel(float* __restrict__ out, int n_dst) {
    int d = (blockIdx.x * blockDim.x + threadIdx.x) >> 5;
    int lane = threadIdx.x & 31;
    if (d >= n_dst) return;
    int h = lane >> 3;

    int i   = g_row[d];
    int end = g_row[d + 1];
    float adv = g_adst[d * HEADS + h];

    float4 acc = make_float4(0.f, 0.f, 0.f, 0.f);
    float wsum = 0.f;
    const float4* feat4 = (const float4*)g_feat;

    int   s_cur = (i < end) ? g_csr_s[i] : 0;
    float a_cur = (i < end) ? g_asrc[s_cur * HEADS + h] : 0.f;
    for (; i < end; ) {
        int inext = i + 1;
        int   s_nxt = 0;
        float a_nxt = 0.f;
        if (inext < end) {
            s_nxt = g_csr_s[inext];
            a_nxt = g_asrc[s_nxt * HEADS + h];
        }
        float w = __expf(leaky02(a_cur + adv));
        float4 f = feat4[s_cur * 32 + lane];
        acc.x += w * f.x; acc.y += w * f.y;
        acc.z += w * f.z; acc.w += w * f.w;
        wsum += w;
        s_cur = s_nxt; a_cur = a_nxt;
        i = inext;
    }

    float rs = 1.f / (wsum + 1e-16f);
    float4* out4 = (float4*)out;
    float4 o = out4[d * 32 + lane];
    o.x += acc.x * rs; o.y += acc.y * rs;
    o.z += acc.z * rs; o.w += acc.w * rs;
    out4[d * 32 + lane] = o;
}

// ============ HMMA GEMM (src), BM=64, occ 2: C=feat, alpha_src from frags ==
#define KS 136
#define A64_BF16 (64 * KS)
#define B_BF16   (128 * KS)
#define SM64_BYTES ((2 * A64_BF16 + 2 * B_BF16) * 2 + 128 * 4)

__global__ __launch_bounds__(256, 2)
void gemm_src_hmma(const float* __restrict__ A,
                   const float* __restrict__ W,     // [K=128, N=128]
                   const float* __restrict__ aux,   // att_src
                   float* __restrict__ C,
                   float* __restrict__ alpha_out,
                   int nrows) {
    extern __shared__ char smem[];
    __nv_bfloat16* Ah = (__nv_bfloat16*)smem;
    __nv_bfloat16* Al = Ah + A64_BF16;
    __nv_bfloat16* Bh = Al + A64_BF16;
    __nv_bfloat16* Bl = Bh + B_BF16;
    float* xtra = (float*)(Bl + B_BF16);

    int tid = threadIdx.x;
    int wid = tid >> 5, lane = tid & 31;
    int m0 = blockIdx.x * 64;

    if (tid < FDIM) xtra[tid] = aux[tid];

    const float4 zero4 = make_float4(0.f, 0.f, 0.f, 0.f);
    // A staging: 64 rows
    for (int idx = tid; idx < 64 * 32; idx += 256) {
        int row = idx >> 5, c4 = (idx & 31) * 4;
        int grow = m0 + row;
        float4 v = (grow < nrows) ? *(const float4*)(A + (size_t)grow * FDIM + c4)
                                  : zero4;
        uint32_t h01, l01, h23, l23;
        split2(v.x, v.y, h01, l01);
        split2(v.z, v.w, h23, l23);
        *(uint2*)(Ah + row * KS + c4) = make_uint2(h01, h23);
        *(uint2*)(Al + row * KS + c4) = make_uint2(l01, l23);
    }
    // B staging: [k][n] from W, coalesced
    for (int idx = tid; idx < 128 * 32; idx += 256) {
        int k = idx >> 5, n4 = (idx & 31) * 4;
        float4 v = *(const float4*)(W + (size_t)k * FDIM + n4);
        uint32_t h01, l01, h23, l23;
        split2(v.x, v.y, h01, l01);
        split2(v.z, v.w, h23, l23);
        *(uint2*)(Bh + k * KS + n4) = make_uint2(h01, h23);
        *(uint2*)(Bl + k * KS + n4) = make_uint2(l01, l23);
    }
    __syncthreads();

    int wm = wid & 1, wn = wid >> 1;     // warp tile: 32 rows x 32 cols
    int g = lane >> 2, q = lane & 3;

    uint32_t ah_b = smem_u32(Ah), al_b = smem_u32(Al);
    uint32_t bh_b = smem_u32(Bh), bl_b = smem_u32(Bl);
    uint32_t a_off = (uint32_t)(((wm * 32 + (lane & 15)) * KS
                                 + ((lane >> 4) << 3)) * 2);
    uint32_t b_off = (uint32_t)(((lane & 15) * KS
                                 + wn * 32 + ((lane >> 4) << 3)) * 2);

    float c[2][4][4];
    #pragma unroll
    for (int mf = 0; mf < 2; mf++)
        #pragma unroll
        for (int nf = 0; nf < 4; nf++)
            #pragma unroll
            for (int r = 0; r < 4; r++) c[mf][nf][r] = 0.f;

    #pragma unroll
    for (int kb8 = 0; kb8 < 8; kb8++) {
        int kb = kb8 * 16;
        uint32_t ah[2][4], al[2][4], bh[2][4], bl[2][4];
        #pragma unroll
        for (int mf = 0; mf < 2; mf++) {
            uint32_t off = a_off + (uint32_t)((mf * 16 * KS + kb) * 2);
            LDM_X4(ah[mf], ah_b + off);
            LDM_X4(al[mf], al_b + off);
        }
        #pragma unroll
        for (int p = 0; p < 2; p++) {
            uint32_t off = b_off + (uint32_t)((kb * KS + p * 16) * 2);
            LDM_X4T(bh[p], bh_b + off);
            LDM_X4T(bl[p], bl_b + off);
        }
        #pragma unroll
        for (int mf = 0; mf < 2; mf++)
            #pragma unroll
            for (int nf = 0; nf < 4; nf++) {
                uint32_t* ph = &bh[nf >> 1][(nf & 1) * 2];
                uint32_t* pl = &bl[nf >> 1][(nf & 1) * 2];
                MMA_BF16(c[mf][nf], ah[mf], ph);
                MMA_BF16(c[mf][nf], ah[mf], pl);
                MMA_BF16(c[mf][nf], al[mf], ph);
            }
    }

    #pragma unroll
    for (int mf = 0; mf < 2; mf++) {
        int row0 = m0 + wm * 32 + mf * 16 + g;
        #pragma unroll
        for (int nf = 0; nf < 4; nf++) {
            int col = wn * 32 + nf * 8 + q * 2;
            if (row0 < nrows)
                *(float2*)(C + (size_t)row0 * FDIM + col) =
                    make_float2(c[mf][nf][0], c[mf][nf][1]);
            if (row0 + 8 < nrows)
                *(float2*)(C + (size_t)(row0 + 8) * FDIM + col) =
                    make_float2(c[mf][nf][2], c[mf][nf][3]);
        }
    }

    int h = wn;
    #pragma unroll
    for (int mf = 0; mf < 2; mf++) {
        float p0 = 0.f, p1 = 0.f;
        #pragma unroll
        for (int nf = 0; nf < 4; nf++) {
            int col = wn * 32 + nf * 8 + q * 2;
            p0 += c[mf][nf][0] * xtra[col] + c[mf][nf][1] * xtra[col + 1];
            p1 += c[mf][nf][2] * xtra[col] + c[mf][nf][3] * xtra[col + 1];
        }
        p0 += __shfl_xor_sync(0xffffffffu, p0, 1);
        p0 += __shfl_xor_sync(0xffffffffu, p0, 2);
        p1 += __shfl_xor_sync(0xffffffffu, p1, 1);
        p1 += __shfl_xor_sync(0xffffffffu, p1, 2);
        if (q == 0) {
            int row0 = m0 + wm * 32 + mf * 16 + g;
            if (row0 < nrows)     alpha_out[row0 * HEADS + h] = p0;
            if (row0 + 8 < nrows) alpha_out[(row0 + 8) * HEADS + h] = p1;
        }
    }
}

// ============ FFMA2 GEMM (dst): C=out+bias, alpha_dst in mainloop (round-8) =
#define BM 128
#define BN 128
#define BK 16
#define TM 8
#define TN 8

__global__ __launch_bounds__(256, 2)
void gemm_dst_ffma2(const float* __restrict__ A,
                    const float* __restrict__ B,
                    const float* __restrict__ aux,   // bias
                    float* __restrict__ C,
                    float* __restrict__ alpha_out,
                    int nrows) {
    __shared__ float As[2][BK][BM];
    __shared__ __align__(16) float Bs[2][BK][BN];
    __shared__ float xtra[FDIM * HEADS];

    int tid = threadIdx.x;
    int tn_idx = tid & 15;
    int tm_idx = tid >> 4;
    int tm0 = tm_idx * TM;
    int tn0 = tn_idx * TN;
    int m0 = blockIdx.x * BM;

    xtra[tid] = g_fold_v[tid];
    xtra[tid + 256] = g_fold_v[tid + 256];

    u64 acc2[TM][TN / 2];
    #pragma unroll
    for (int i = 0; i < TM; i++)
        #pragma unroll
        for (int j = 0; j < TN / 2; j++) acc2[i][j] = 0ull;

    int af_row[2], af_k4[2];
    int bf_k[2], bf_n4[2];
    #pragma unroll
    for (int i = 0; i < 2; i++) {
        int f = tid + i * 256;
        af_row[i] = f >> 2;
        af_k4[i]  = (f & 3) * 4;
        bf_k[i]   = f >> 5;
        bf_n4[i]  = (f & 31) * 4;
    }

    float4 a_reg[2], b_reg[2];
    const float4 zero4 = make_float4(0.f, 0.f, 0.f, 0.f);

    #pragma unroll
    for (int i = 0; i < 2; i++) {
        int grow = m0 + af_row[i];
        a_reg[i] = (grow < nrows)
            ? *(const float4*)(A + (size_t)grow * FDIM + af_k4[i]) : zero4;
        b_reg[i] = *(const float4*)(B + (size_t)bf_k[i] * FDIM + bf_n4[i]);
    }
    #pragma unroll
    for (int i = 0; i < 2; i++) {
        As[0][af_k4[i] + 0][af_row[i]] = a_reg[i].x;
        As[0][af_k4[i] + 1][af_row[i]] = a_reg[i].y;
        As[0][af_k4[i] + 2][af_row[i]] = a_reg[i].z;
        As[0][af_k4[i] + 3][af_row[i]] = a_reg[i].w;
        *(float4*)&Bs[0][bf_k[i]][bf_n4[i]] = b_reg[i];
    }
    __syncthreads();

    int h  = tn_idx >> 2;
    int qq = (tn_idx & 3) * 2;
    float av0 = 0.f, av1 = 0.f;

    int buf = 0;
    const int NT = FDIM / BK;
    for (int t = 0; t < NT; t++) {
        if (t + 1 < NT) {
            int kt = (t + 1) * BK;
            #pragma unroll
            for (int i = 0; i < 2; i++) {
                int grow = m0 + af_row[i];
                a_reg[i] = (grow < nrows)
                    ? *(const float4*)(A + (size_t)grow * FDIM + kt + af_k4[i]) : zero4;
                b_reg[i] = *(const float4*)(B + (size_t)(kt + bf_k[i]) * FDIM + bf_n4[i]);
            }
        }

        #pragma unroll
        for (int k = 0; k < BK; k++) {
            float4 a0 = *(const float4*)&As[buf][k][tm0];
            float4 a1 = *(const float4*)&As[buf][k][tm0 + 4];
            ulonglong2 bq0 = *(const ulonglong2*)&Bs[buf][k][tn0];
            ulonglong2 bq1 = *(const ulonglong2*)&Bs[buf][k][tn0 + 4];
            u64 bp[4] = {bq0.x, bq0.y, bq1.x, bq1.y};
            float avv[TM] = {a0.x, a0.y, a0.z, a0.w, a1.x, a1.y, a1.z, a1.w};
            #pragma unroll
            for (int i = 0; i < TM; i++) {
                u64 ad;
                PACK_DUP_F32X2(ad, avv[i]);
                #pragma unroll
                for (int j = 0; j < TN / 2; j++)
                    FMA_F32X2(acc2[i][j], ad, bp[j], acc2[i][j]);
            }
            float vv = xtra[(t * BK + k) * HEADS + h];
            av0 += As[buf][k][tm0 + qq]     * vv;
            av1 += As[buf][k][tm0 + qq + 1] * vv;
        }

        if (t + 1 < NT) {
            int nb = buf ^ 1;
            #pragma unroll
            for (int i = 0; i < 2; i++) {
                As[nb][af_k4[i] + 0][af_row[i]] = a_reg[i].x;
                As[nb][af_k4[i] + 1][af_row[i]] = a_reg[i].y;
                As[nb][af_k4[i] + 2][af_row[i]] = a_reg[i].z;
                As[nb][af_k4[i] + 3][af_row[i]] = a_reg[i].w;
                *(float4*)&Bs[nb][bf_k[i]][bf_n4[i]] = b_reg[i];
            }
            __syncthreads();
            buf = nb;
        }
    }

    float acc[TM][TN];
    #pragma unroll
    for (int i = 0; i < TM; i++)
        #pragma unroll
        for (int j = 0; j < TN / 2; j++) {
            unsigned lo, hi;
            UNPACK_F32X2(lo, hi, acc2[i][j]);
            acc[i][2 * j]     = __uint_as_float(lo);
            acc[i][2 * j + 1] = __uint_as_float(hi);
        }

    float4 bb0 = *(const float4*)(aux + tn0);
    float4 bb1 = *(const float4*)(aux + tn0 + 4);
    #pragma unroll
    for (int i = 0; i < TM; i++) {
        int row = m0 + tm0 + i;
        if (row < nrows) {
            float4 o0 = make_float4(acc[i][0] + bb0.x, acc[i][1] + bb0.y,
                                    acc[i][2] + bb0.z, acc[i][3] + bb0.w);
            float4 o1 = make_float4(acc[i][4] + bb1.x, acc[i][5] + bb1.y,
                                    acc[i][6] + bb1.z, acc[i][7] + bb1.w);
            *(float4*)(C + (size_t)row * FDIM + tn0)     = o0;
            *(float4*)(C + (size_t)row * FDIM + tn0 + 4) = o1;
        }
    }

    int r0 = m0 + tm0 + qq;
    if (r0 < nrows)     alpha_out[r0 * HEADS + h]       = av0;
    if (r0 + 1 < nrows) alpha_out[(r0 + 1) * HEADS + h] = av1;
}

// ---------------------------------------------------------------------------
extern "C" void kernel_launch(void* const* d_in, const int* in_sizes, int n_in,
                              void* d_out, int out_size) {
    const float* x_src    = (const float*)d_in[0];
    const float* x_dst    = (const float*)d_in[1];
    const int*   edge_src = (const int*)d_in[2];
    const int*   edge_dst = (const int*)d_in[3];
    int off = (n_in >= 11) ? 5 : 4;
    const float* W_src   = (const float*)d_in[off + 0];
    const float* W_dst   = (const float*)d_in[off + 1];
    const float* att_src = (const float*)d_in[off + 2];
    const float* att_dst = (const float*)d_in[off + 3];
    const float* W_self  = (const float*)d_in[off + 4];
    const float* b_self  = (const float*)d_in[off + 5];
    float* out = (float*)d_out;

    int n_src = in_sizes[0] / FDIM;
    int n_dst = in_sizes[1] / FDIM;
    int E     = in_sizes[2];

    static float* p_feat = nullptr;
    static float* p_asrc = nullptr;
    static float* p_adst = nullptr;
    static cudaStream_t s1 = nullptr, s2 = nullptr;
    static cudaEvent_t ev_fork = nullptr, ev_g1 = nullptr, ev_csr = nullptr;
    if (!p_feat) {
        cudaGetSymbolAddress((void**)&p_feat, g_feat);
        cudaGetSymbolAddress((void**)&p_asrc, g_asrc);
        cudaGetSymbolAddress((void**)&p_adst, g_adst);
        cudaStreamCreateWithFlags(&s1, cudaStreamNonBlocking);
        cudaStreamCreateWithFlags(&s2, cudaStreamNonBlocking);
        cudaEventCreateWithFlags(&ev_fork, cudaEventDisableTiming);
        cudaEventCreateWithFlags(&ev_g1,   cudaEventDisableTiming);
        cudaEventCreateWithFlags(&ev_csr,  cudaEventDisableTiming);
        cudaFuncSetAttribute(gemm_src_hmma,
            cudaFuncAttributeMaxDynamicSharedMemorySize, SM64_BYTES);
    }

    int nb = (n_dst + SCAN_TILE - 1) / SCAN_TILE;

    // main: fold (needed by gemm_dst)
    fold_kernel<<<1, 128>>>(W_dst, att_dst);

    cudaEventRecord(ev_fork, 0);
    cudaStreamWaitEvent(s1, ev_fork, 0);
    cudaStreamWaitEvent(s2, ev_fork, 0);

    // s2: CSR build
    zero_deg_kernel<<<(n_dst + 255) / 256, 256, 0, s2>>>(n_dst);
    hist_kernel<<<(E + 255) / 256, 256, 0, s2>>>(edge_dst, E);
    scan_local_kernel<<<nb, 256, 0, s2>>>(n_dst);
    scan_bsum_kernel<<<1, 256, 0, s2>>>(nb, n_dst);
    scan_apply_kernel<<<nb, 256, 0, s2>>>(n_dst);
    scatter_kernel<<<(E + 255) / 256, 256, 0, s2>>>(edge_src, edge_dst, E);
    cudaEventRecord(ev_csr, s2);

    // s1: dst GEMM on the FMA pipe (FFMA2)
    gemm_dst_ffma2<<<(n_dst + BM - 1) / BM, 256, 0, s1>>>(
        x_dst, W_self, b_self, out, p_adst, n_dst);
    cudaEventRecord(ev_g1, s1);

    // main: src GEMM on the tensor pipe (HMMA, BM=64, occ 2)
    gemm_src_hmma<<<(n_src + 63) / 64, 256, SM64_BYTES>>>(
        x_src, W_src, att_src, p_feat, p_asrc, n_src);

    // join
    cudaStreamWaitEvent(0, ev_g1, 0);
    cudaStreamWaitEvent(0, ev_csr, 0);
    long long total_threads = (long long)n_dst * 32;
    int blocks = (int)((total_threads + 255) / 256);
    aggr_kernel<<<blocks, 256>>>(out, n_dst);
}